// round 2
// baseline (speedup 1.0000x reference)
#include <cuda_runtime.h>
#include <math.h>

#define SZ 160
#define NB 8
#define NC 64
#define HW 256
#define CCHUNKS 32
#define CPER 2          // NC / CCHUNKS
#define KTILE 16

// -------- scratch (no allocations allowed; __device__ globals) --------
__device__ float g_x160[NB * NC * SZ * SZ];                 // 52.4 MB
__device__ float g_part[2 * CCHUNKS * NB * NC * SZ];        // 21 MB split-K partials
__device__ float g_bvec[NB * NC * SZ];
__device__ float g_cvec[NB * NC * SZ];
__device__ float g_s[NB * NC];

// ---------------- Kernel 1: nearest downsample 256->160 ----------------
// hi = (h*256)//160 == (h*8)//5 ; wi likewise.
__global__ void k_down(const float* __restrict__ x) {
    int bc = blockIdx.x;  // 0..511 = batch*NC + ch
    const float* __restrict__ src = x + (size_t)bc * HW * HW;
    float* __restrict__ dst = g_x160 + (size_t)bc * SZ * SZ;
    for (int e = threadIdx.x; e < SZ * SZ; e += blockDim.x) {
        int h = e / SZ;
        int w = e - h * SZ;
        int hi = (h * 8) / 5;
        int wi = (w * 8) / 5;
        dst[e] = __ldg(&src[hi * HW + wi]);
    }
}

// ---------------- Kernel 2: split-K GEMMs ----------------
// which==0: b_pre[b,o,h] = sum_{c,w} x160[b,c,h,w] * Wb[o,c,w]   (m=h, k=w)
// which==1: c_pre[b,o,w] = sum_{c,h} x160[b,c,h,w] * Wc[o,c,h]   (m=w, k=h)
// Block: 160 threads, block tile M=160 x N=64, 8x8 per-thread register tile.
// Split-K over channel chunks (CPER channels per block).
__global__ __launch_bounds__(160, 4)
void k_gemm(const float* __restrict__ WbP, const float* __restrict__ WcP) {
    __shared__ __align__(16) float As[KTILE * 164];  // [kk][m], padded row 164
    __shared__ __align__(16) float Bs[KTILE * 68];   // [kk][o], padded row 68

    const int cc    = blockIdx.x;   // 0..CCHUNKS-1
    const int batch = blockIdx.y;   // 0..7
    const int which = blockIdx.z;   // 0 or 1
    const float* __restrict__ W = which ? WcP : WbP;

    const int t  = threadIdx.x;     // 0..159
    const int ty = t >> 3;          // 0..19 -> m block of 8
    const int tx = t & 7;           // 0..7  -> n block of 8

    float acc[8][8];
#pragma unroll
    for (int i = 0; i < 8; i++)
#pragma unroll
        for (int j = 0; j < 8; j++) acc[i][j] = 0.f;

    for (int cl = 0; cl < CPER; cl++) {
        const int c = cc * CPER + cl;
        const float* __restrict__ xb = g_x160 + (size_t)(batch * NC + c) * SZ * SZ;
        const float* __restrict__ wb = W + (size_t)c * SZ;  // W[o*NC*SZ + c*SZ + k]

        for (int k0 = 0; k0 < SZ; k0 += KTILE) {
            // ---- load A tile into As[kk][m] ----
            if (which == 0) {
                // A[m=h][k=w]: x160 row-contiguous in k; transpose into As
#pragma unroll
                for (int i = 0; i < 16; i++) {
                    int e  = i * 160 + t;
                    int m  = e >> 4;
                    int kk = e & 15;
                    As[kk * 164 + m] = xb[m * SZ + k0 + kk];
                }
            } else {
                // A[m=w][k=h]: x160 row h is contiguous in m; direct copy
#pragma unroll
                for (int i = 0; i < 16; i++) {
                    As[i * 164 + t] = xb[(k0 + i) * SZ + t];
                }
            }
            // ---- load B tile into Bs[kk][o] ----
            for (int e = t; e < KTILE * NC; e += 160) {
                int o  = e >> 4;
                int kk = e & 15;
                Bs[kk * 68 + o] = wb[(size_t)o * (NC * SZ) + k0 + kk];
            }
            __syncthreads();

#pragma unroll 4
            for (int kk = 0; kk < KTILE; kk++) {
                float4 a0 = *(const float4*)&As[kk * 164 + ty * 8];
                float4 a1 = *(const float4*)&As[kk * 164 + ty * 8 + 4];
                float4 b0 = *(const float4*)&Bs[kk * 68 + tx * 8];
                float4 b1 = *(const float4*)&Bs[kk * 68 + tx * 8 + 4];
                float am[8] = {a0.x, a0.y, a0.z, a0.w, a1.x, a1.y, a1.z, a1.w};
                float bn[8] = {b0.x, b0.y, b0.z, b0.w, b1.x, b1.y, b1.z, b1.w};
#pragma unroll
                for (int mi = 0; mi < 8; mi++)
#pragma unroll
                    for (int ni = 0; ni < 8; ni++)
                        acc[mi][ni] = fmaf(am[mi], bn[ni], acc[mi][ni]);
            }
            __syncthreads();
        }
    }

    // ---- write partials: g_part[(which*CCHUNKS+cc)*NB + batch][o*SZ + m] ----
    float* __restrict__ pout =
        g_part + ((size_t)(which * CCHUNKS + cc) * NB + batch) * (NC * SZ);
#pragma unroll
    for (int ni = 0; ni < 8; ni++) {
        int o = tx * 8 + ni;
#pragma unroll
        for (int mi = 0; mi < 8; mi += 4) {
            float4 v = make_float4(acc[mi][ni], acc[mi + 1][ni],
                                   acc[mi + 2][ni], acc[mi + 3][ni]);
            *(float4*)&pout[o * SZ + ty * 8 + mi] = v;
        }
    }
}

// ---------------- Kernel 3: reduce partials, BN-fold, SiLU, s = <b,c> ----------------
__global__ void k_finish(const float* __restrict__ gb, const float* __restrict__ bb,
                         const float* __restrict__ gc, const float* __restrict__ bc) {
    const int o     = blockIdx.x;   // channel
    const int batch = blockIdx.y;
    const int t     = threadIdx.x;  // 0..159 (position)

    float bsum = 0.f, csum = 0.f;
    const size_t inner = (size_t)o * SZ + t;
    for (int cc = 0; cc < CCHUNKS; cc++) {
        bsum += g_part[((size_t)(cc) * NB + batch) * (NC * SZ) + inner];
        csum += g_part[((size_t)(CCHUNKS + cc) * NB + batch) * (NC * SZ) + inner];
    }
    float bp = bsum * gb[o] + bb[o];
    float bv = bp / (1.f + expf(-bp));
    float cp = csum * gc[o] + bc[o];
    float cv = cp / (1.f + expf(-cp));

    const size_t idx = (size_t)(batch * NC + o) * SZ + t;
    g_bvec[idx] = bv;
    g_cvec[idx] = cv;

    __shared__ float red[SZ];
    red[t] = bv * cv;
    __syncthreads();
    if (t == 0) {
        float s = 0.f;
        for (int i = 0; i < SZ; i++) s += red[i];
        g_s[batch * NC + o] = s;
    }
}

// ---------------- Kernel 4: rank-1 update + nearest upsample 160->256 ----------------
// out[Y,X] = x160[h,wi] + (x160[h,:]·b)*s*c[wi],  h=(Y*5)//8, wi=(X*5)//8
// Static smem only (no cudaFuncSetAttribute, graph-capture safe); x160 reads
// come from global (L2-resident: whole buffer is 52 MB < 126 MB L2, written
// by k_down in the same launch sequence).
__global__ __launch_bounds__(256, 4)
void k_final(float* __restrict__ out) {
    __shared__ float bv[SZ];
    __shared__ float cv[SZ];
    __shared__ float ps[SZ];   // (x160[h,:]·b) * s

    const int bc = blockIdx.x;      // batch*NC + ch
    const int t  = threadIdx.x;     // 0..255
    const float* __restrict__ xsrc = g_x160 + (size_t)bc * SZ * SZ;

    if (t < SZ) {
        bv[t] = g_bvec[(size_t)bc * SZ + t];
        cv[t] = g_cvec[(size_t)bc * SZ + t];
    }
    __syncthreads();

    const float sval = g_s[bc];
    const int warp = t >> 5, lane = t & 31;
    // p[h] = sum_w x160[h,w]*b[w]; one warp per row, rows strided by 8 warps
    for (int h = warp; h < SZ; h += 8) {
        float p = 0.f;
#pragma unroll
        for (int k = 0; k < 5; k++) {
            int w = lane + 32 * k;
            p += xsrc[h * SZ + w] * bv[w];
        }
#pragma unroll
        for (int off = 16; off; off >>= 1) p += __shfl_down_sync(0xffffffffu, p, off);
        if (lane == 0) ps[h] = p * sval;
    }
    __syncthreads();

    float* __restrict__ obase = out + (size_t)bc * HW * HW;
    const int X  = t;
    const int wi = (X * 5) >> 3;
    const float cw = cv[wi];
#pragma unroll 4
    for (int Y = 0; Y < HW; Y++) {
        int h = (Y * 5) >> 3;
        obase[Y * HW + X] = xsrc[h * SZ + wi] + ps[h] * cw;
    }
}

// ---------------- launch ----------------
extern "C" void kernel_launch(void* const* d_in, const int* in_sizes, int n_in,
                              void* d_out, int out_size) {
    const float* x  = (const float*)d_in[0];
    const float* Wb = (const float*)d_in[1];
    const float* Wc = (const float*)d_in[2];
    const float* gb = (const float*)d_in[3];
    const float* bb = (const float*)d_in[4];
    const float* gc = (const float*)d_in[5];
    const float* bc = (const float*)d_in[6];
    float* out = (float*)d_out;

    k_down<<<NB * NC, 256>>>(x);
    k_gemm<<<dim3(CCHUNKS, NB, 2), 160>>>(Wb, Wc);
    k_finish<<<dim3(NC, NB), 160>>>(gb, bb, gc, bc);
    k_final<<<NB * NC, 256>>>(out);
}

// round 5
// speedup vs baseline: 1.1713x; 1.1713x over previous
#include <cuda_runtime.h>
#include <math.h>

#define SZ 160
#define NB 8
#define NC 64
#define HW 256
#define CCHUNKS 32
#define CPER 2          // NC / CCHUNKS
#define KTILE 16

// -------- scratch (no allocations allowed; __device__ globals) --------
__device__ float g_x160[NB * NC * SZ * SZ];                 // 52.4 MB
__device__ float g_part[2 * CCHUNKS * NB * NC * SZ];        // 21 MB split-K partials
__device__ float g_bvec[NB * NC * SZ];
__device__ float g_cvec[NB * NC * SZ];
__device__ float g_s[NB * NC];

// ---------------- Kernel 1: nearest downsample 256->160 ----------------
// (exact R1 known-passing version)
__global__ void k_down(const float* __restrict__ x) {
    int bc = blockIdx.x;  // 0..511 = batch*NC + ch
    const float* __restrict__ src = x + (size_t)bc * HW * HW;
    float* __restrict__ dst = g_x160 + (size_t)bc * SZ * SZ;
    for (int e = threadIdx.x; e < SZ * SZ; e += blockDim.x) {
        int h = e / SZ;
        int w = e - h * SZ;
        int hi = (h * 8) / 5;
        int wi = (w * 8) / 5;
        dst[e] = __ldg(&src[hi * HW + wi]);
    }
}

// ---------------- Kernel 2: split-K GEMMs ----------------
// which==0: b_pre[b,o,h] = sum_{c,w} x160[b,c,h,w] * Wb[o,c,w]   (m=h, k=w)
// which==1: c_pre[b,o,w] = sum_{c,h} x160[b,c,h,w] * Wc[o,c,h]   (m=w, k=h)
// (exact R1 known-passing version)
__global__ __launch_bounds__(160, 4)
void k_gemm(const float* __restrict__ WbP, const float* __restrict__ WcP) {
    __shared__ __align__(16) float As[KTILE * 164];  // [kk][m], padded row 164
    __shared__ __align__(16) float Bs[KTILE * 68];   // [kk][o], padded row 68

    const int cc    = blockIdx.x;   // 0..CCHUNKS-1
    const int batch = blockIdx.y;   // 0..7
    const int which = blockIdx.z;   // 0 or 1
    const float* __restrict__ W = which ? WcP : WbP;

    const int t  = threadIdx.x;     // 0..159
    const int ty = t >> 3;          // 0..19 -> m block of 8
    const int tx = t & 7;           // 0..7  -> n block of 8

    float acc[8][8];
#pragma unroll
    for (int i = 0; i < 8; i++)
#pragma unroll
        for (int j = 0; j < 8; j++) acc[i][j] = 0.f;

    for (int cl = 0; cl < CPER; cl++) {
        const int c = cc * CPER + cl;
        const float* __restrict__ xb = g_x160 + (size_t)(batch * NC + c) * SZ * SZ;
        const float* __restrict__ wb = W + (size_t)c * SZ;  // W[o*NC*SZ + c*SZ + k]

        for (int k0 = 0; k0 < SZ; k0 += KTILE) {
            if (which == 0) {
#pragma unroll
                for (int i = 0; i < 16; i++) {
                    int e  = i * 160 + t;
                    int m  = e >> 4;
                    int kk = e & 15;
                    As[kk * 164 + m] = xb[m * SZ + k0 + kk];
                }
            } else {
#pragma unroll
                for (int i = 0; i < 16; i++) {
                    As[i * 164 + t] = xb[(k0 + i) * SZ + t];
                }
            }
            for (int e = t; e < KTILE * NC; e += 160) {
                int o  = e >> 4;
                int kk = e & 15;
                Bs[kk * 68 + o] = wb[(size_t)o * (NC * SZ) + k0 + kk];
            }
            __syncthreads();

#pragma unroll 4
            for (int kk = 0; kk < KTILE; kk++) {
                float4 a0 = *(const float4*)&As[kk * 164 + ty * 8];
                float4 a1 = *(const float4*)&As[kk * 164 + ty * 8 + 4];
                float4 b0 = *(const float4*)&Bs[kk * 68 + tx * 8];
                float4 b1 = *(const float4*)&Bs[kk * 68 + tx * 8 + 4];
                float am[8] = {a0.x, a0.y, a0.z, a0.w, a1.x, a1.y, a1.z, a1.w};
                float bn[8] = {b0.x, b0.y, b0.z, b0.w, b1.x, b1.y, b1.z, b1.w};
#pragma unroll
                for (int mi = 0; mi < 8; mi++)
#pragma unroll
                    for (int ni = 0; ni < 8; ni++)
                        acc[mi][ni] = fmaf(am[mi], bn[ni], acc[mi][ni]);
            }
            __syncthreads();
        }
    }

    float* __restrict__ pout =
        g_part + ((size_t)(which * CCHUNKS + cc) * NB + batch) * (NC * SZ);
#pragma unroll
    for (int ni = 0; ni < 8; ni++) {
        int o = tx * 8 + ni;
#pragma unroll
        for (int mi = 0; mi < 8; mi += 4) {
            float4 v = make_float4(acc[mi][ni], acc[mi + 1][ni],
                                   acc[mi + 2][ni], acc[mi + 3][ni]);
            *(float4*)&pout[o * SZ + ty * 8 + mi] = v;
        }
    }
}

// ---------------- Kernel 3: reduce partials, BN-fold, SiLU, s = <b,c> ----------------
__global__ void k_finish(const float* __restrict__ gb, const float* __restrict__ bb,
                         const float* __restrict__ gc, const float* __restrict__ bc) {
    const int o     = blockIdx.x;   // channel
    const int batch = blockIdx.y;
    const int t     = threadIdx.x;  // 0..159

    float bsum = 0.f, csum = 0.f;
    const size_t inner = (size_t)o * SZ + t;
    for (int cc = 0; cc < CCHUNKS; cc++) {
        bsum += g_part[((size_t)(cc) * NB + batch) * (NC * SZ) + inner];
        csum += g_part[((size_t)(CCHUNKS + cc) * NB + batch) * (NC * SZ) + inner];
    }
    float bp = bsum * gb[o] + bb[o];
    float bv = bp / (1.f + expf(-bp));
    float cp = csum * gc[o] + bc[o];
    float cv = cp / (1.f + expf(-cp));

    const size_t idx = (size_t)(batch * NC + o) * SZ + t;
    g_bvec[idx] = bv;
    g_cvec[idx] = cv;

    __shared__ float red[SZ];
    red[t] = bv * cv;
    __syncthreads();
    if (t == 0) {
        float s = 0.f;
        for (int i = 0; i < SZ; i++) s += red[i];
        g_s[batch * NC + o] = s;
    }
}

// ---------------- Kernel 4: rank-1 update + nearest upsample 160->256 ----------------
// out[Y,X] = x160[h,wi] + ps[h]*cv[wi],  h=(Y*5)>>3, wi=(X*5)>>3,
// ps[h] = (x160[h,:]·b)*s.  float4 stores, 4 rows per iteration, MLP ~8.
__global__ __launch_bounds__(256, 6)
void k_final(float* __restrict__ out) {
    __shared__ float bv[SZ];
    __shared__ float cvE[HW];   // cv[wi(X)] pre-expanded
    __shared__ float ps[SZ];

    const int bc = blockIdx.x;      // batch*NC + ch
    const int t  = threadIdx.x;     // 0..255
    const float* __restrict__ xsrc = g_x160 + (size_t)bc * SZ * SZ;

    if (t < SZ) bv[t] = g_bvec[(size_t)bc * SZ + t];
    cvE[t] = g_cvec[(size_t)bc * SZ + ((t * 5) >> 3)];
    __syncthreads();

    const float sval = g_s[bc];
    const int warp = t >> 5, lane = t & 31;
    for (int h = warp; h < SZ; h += 8) {
        float p = 0.f;
#pragma unroll
        for (int k = 0; k < 5; k++) {
            int w = lane + 32 * k;
            p += xsrc[h * SZ + w] * bv[w];
        }
#pragma unroll
        for (int off = 16; off; off >>= 1) p += __shfl_down_sync(0xffffffffu, p, off);
        if (lane == 0) ps[h] = p * sval;
    }
    __syncthreads();

    // main loop: 4 output rows per iteration; thread -> (row r, float4 xq)
    const int r  = t >> 6;          // 0..3
    const int xq = t & 63;          // float4 column
    const int X0 = xq * 4;
    const int wi0 = (X0 * 5) >> 3;
    const int wi1 = ((X0 + 1) * 5) >> 3;
    const int wi2 = ((X0 + 2) * 5) >> 3;
    const int wi3 = ((X0 + 3) * 5) >> 3;
    const float c0 = cvE[X0], c1 = cvE[X0 + 1], c2 = cvE[X0 + 2], c3 = cvE[X0 + 3];

    float* __restrict__ obase = out + (size_t)bc * HW * HW;
#pragma unroll 2
    for (int Y0 = 0; Y0 < HW; Y0 += 4) {
        const int Y = Y0 + r;
        const int h = (Y * 5) >> 3;
        const float* __restrict__ xr = xsrc + h * SZ;
        const float pv = ps[h];
        float4 v;
        v.x = xr[wi0] + pv * c0;
        v.y = xr[wi1] + pv * c1;
        v.z = xr[wi2] + pv * c2;
        v.w = xr[wi3] + pv * c3;
        *(float4*)&obase[Y * HW + X0] = v;
    }
}

// ---------------- launch ----------------
extern "C" void kernel_launch(void* const* d_in, const int* in_sizes, int n_in,
                              void* d_out, int out_size) {
    const float* x  = (const float*)d_in[0];
    const float* Wb = (const float*)d_in[1];
    const float* Wc = (const float*)d_in[2];
    const float* gb = (const float*)d_in[3];
    const float* bb = (const float*)d_in[4];
    const float* gc = (const float*)d_in[5];
    const float* bc = (const float*)d_in[6];
    float* out = (float*)d_out;

    k_down<<<NB * NC, 256>>>(x);
    k_gemm<<<dim3(CCHUNKS, NB, 2), 160>>>(Wb, Wc);
    k_finish<<<dim3(NC, NB), 160>>>(gb, bb, gc, bc);
    k_final<<<NB * NC, 256>>>(out);
}